// round 9
// baseline (speedup 1.0000x reference)
#include <cuda_runtime.h>
#include <cuda_bf16.h>
#include <cuda_fp16.h>
#include <cstdint>
#include <cstddef>

// DotAttention B=16, T=1024, D=1024 fp32 (plain sm_100, mma.sync path).
// QK^T: fp16 2-term (Qh*Kh + Ql*Kh), 512 threads / 16 warps, 4-stage pipeline.
// P*V : fp16 single-pass, 2 CTAs/SM.

#define BATCH 16
#define TSEQ  1024
#define DDIM  1024
#define NT    8
static constexpr float SCALE = 0.03125f;

#define NELEM ((size_t)BATCH * TSEQ * DDIM)   // 16M

__device__ __align__(16) __half g_Qhi[NELEM];
__device__ __align__(16) __half g_Qlo[NELEM];
__device__ __align__(16) __half g_Kf16[NELEM];
__device__ __align__(16) __half g_Vtf16[NELEM];  // V^T per batch: [b][d][s]
__device__ __align__(16) __half g_Pf16[NELEM];   // normalized P fp16
__device__ float g_rowpart[BATCH * TSEQ * NT];

// ---------------------------------------------------------------------------
__device__ __forceinline__ uint32_t smem_u32(const void* p) {
    uint32_t a;
    asm("{ .reg .u64 t; cvta.to.shared.u64 t, %1; cvt.u32.u64 %0, t; }" : "=r"(a) : "l"(p));
    return a;
}
__device__ __forceinline__ void cp16(uint32_t dst, const void* src) {
    asm volatile("cp.async.cg.shared.global [%0], [%1], 16;" :: "r"(dst), "l"(src));
}
__device__ __forceinline__ void cp_commit() { asm volatile("cp.async.commit_group;" ::: "memory"); }
template <int N> __device__ __forceinline__ void cp_wait() {
    asm volatile("cp.async.wait_group %0;" :: "n"(N) : "memory");
}
__device__ __forceinline__ void ldsm4(uint32_t (&r)[4], uint32_t addr) {
    asm volatile("ldmatrix.sync.aligned.m8n8.x4.shared.b16 {%0,%1,%2,%3}, [%4];"
        : "=r"(r[0]), "=r"(r[1]), "=r"(r[2]), "=r"(r[3]) : "r"(addr));
}
__device__ __forceinline__ void mma_f16(float (&d)[4], const uint32_t (&a)[4],
                                        uint32_t b0, uint32_t b1) {
    asm volatile(
        "mma.sync.aligned.m16n8k16.row.col.f32.f16.f16.f32 "
        "{%0,%1,%2,%3}, {%4,%5,%6,%7}, {%8,%9}, {%0,%1,%2,%3};"
        : "+f"(d[0]), "+f"(d[1]), "+f"(d[2]), "+f"(d[3])
        : "r"(a[0]), "r"(a[1]), "r"(a[2]), "r"(a[3]), "r"(b0), "r"(b1));
}
#define SW128(o) ((o) ^ (((o) >> 3) & 0x70))

// ---------------------------------------------------------------------------
// conv Q: fp32 -> (hi, lo) fp16
// ---------------------------------------------------------------------------
__global__ __launch_bounds__(256) void conv_q(const float* __restrict__ x) {
    size_t i = ((size_t)blockIdx.x * 256 + threadIdx.x) * 4;
    float4 v = *(const float4*)(x + i);
    __half h0 = __float2half_rn(v.x), h1 = __float2half_rn(v.y);
    __half h2 = __float2half_rn(v.z), h3 = __float2half_rn(v.w);
    __half l0 = __float2half_rn(v.x - __half2float(h0));
    __half l1 = __float2half_rn(v.y - __half2float(h1));
    __half l2 = __float2half_rn(v.z - __half2float(h2));
    __half l3 = __float2half_rn(v.w - __half2float(h3));
    __half2 hp0(h0, h1), hp1(h2, h3), lp0(l0, l1), lp1(l2, l3);
    *(uint2*)(g_Qhi + i) = make_uint2(*(uint32_t*)&hp0, *(uint32_t*)&hp1);
    *(uint2*)(g_Qlo + i) = make_uint2(*(uint32_t*)&lp0, *(uint32_t*)&lp1);
}

// conv K: fp32 -> fp16 single
__global__ __launch_bounds__(256) void conv_k(const float* __restrict__ x) {
    size_t i = ((size_t)blockIdx.x * 256 + threadIdx.x) * 4;
    float4 v = *(const float4*)(x + i);
    __half2 p0 = __floats2half2_rn(v.x, v.y);
    __half2 p1 = __floats2half2_rn(v.z, v.w);
    *(uint2*)(g_Kf16 + i) = make_uint2(*(uint32_t*)&p0, *(uint32_t*)&p1);
}

// ---------------------------------------------------------------------------
// vtrans: V [b][s][d] -> V^T fp16 [b][d][s]
// ---------------------------------------------------------------------------
__global__ __launch_bounds__(256) void vtrans(const float* __restrict__ V) {
    __shared__ float tile[32][33];
    int b = blockIdx.z, s0 = blockIdx.y * 32, d0 = blockIdx.x * 32;
    int t = threadIdx.x;
    int r = t >> 3, c4 = t & 7;
    const float* Vb = V + ((size_t)b * TSEQ + s0) * DDIM + d0;
    float4 v = *(const float4*)(Vb + (size_t)r * DDIM + c4 * 4);
    tile[r][c4 * 4 + 0] = v.x; tile[r][c4 * 4 + 1] = v.y;
    tile[r][c4 * 4 + 2] = v.z; tile[r][c4 * 4 + 3] = v.w;
    __syncthreads();
    int dr = t >> 3, s4 = t & 7;
    float x0 = tile[s4 * 4 + 0][dr], x1 = tile[s4 * 4 + 1][dr];
    float x2 = tile[s4 * 4 + 2][dr], x3 = tile[s4 * 4 + 3][dr];
    __half2 p0 = __floats2half2_rn(x0, x1);
    __half2 p1 = __floats2half2_rn(x2, x3);
    size_t off = ((size_t)b * DDIM + d0 + dr) * TSEQ + s0 + s4 * 4;
    *(uint2*)(g_Vtf16 + off) = make_uint2(*(uint32_t*)&p0, *(uint32_t*)&p1);
}

// ---------------------------------------------------------------------------
// QK^T: C[128,128] = Q[128,1024] K[128,1024]^T, fp16 2-term.
// 512 threads / 16 warps = 4m x 4n, warp tile 32x32. 4-stage k64 pipeline.
// Epilogue: exp, rowsums, staged coalesced store.
// ---------------------------------------------------------------------------
#define QK_STAGE 49152
#define QK_SMEM  (4 * QK_STAGE + 2048)
#define QK_RED   (4 * QK_STAGE)

__global__ void __launch_bounds__(512, 1) qk_gemm(float* __restrict__ out) {
    extern __shared__ __align__(1024) char smem[];
    const uint32_t sb = smem_u32(smem);
    const int t = threadIdx.x, wid = t >> 5, lane = t & 31;
    const int tn = blockIdx.x, tm = blockIdx.y, b = blockIdx.z;

    const size_t aoff = ((size_t)b * TSEQ + tm * 128) * 1024;
    const size_t boff = ((size_t)b * TSEQ + tn * 128) * 1024;
    const __half* srcs[3] = {g_Qhi + aoff, g_Qlo + aoff, g_Kf16 + boff};

    // producer: 512 threads, each loads rows lr and lr+64 (swizzle-invariant +8192B)
    const int lr = t >> 3;          // 0..63
    const int lc = t & 7;
    const uint32_t dsw = SW128((uint32_t)(lr * 128 + lc * 16));

    auto load_stage = [&](int slot, int k0) {
        const uint32_t s0 = sb + slot * QK_STAGE;
        #pragma unroll
        for (int buf = 0; buf < 3; buf++) {
            const __half* p = srcs[buf] + k0 + lc * 8;
            cp16(s0 + buf * 16384 + dsw,        p + (size_t)lr * 1024);
            cp16(s0 + buf * 16384 + dsw + 8192, p + (size_t)(lr + 64) * 1024);
        }
        cp_commit();
    };

    const int warp_m = wid >> 2, warp_n = wid & 3;      // 4x4 warps, 32x32 tiles
    const int mrow = lane & 7, mid = lane >> 3;
    const int arow_base = warp_m * 32 + mrow + (mid & 1) * 8;
    const int a_k8 = mid >> 1;
    const int brow_base = warp_n * 32 + mrow + (mid >> 1) * 8;
    const int b_k8 = mid & 1;

    float acc[2][4][4] = {};

    load_stage(0, 0);
    load_stage(1, 64);
    load_stage(2, 128);

    for (int i = 0; i < 16; i++) {
        if (i < 14) cp_wait<2>(); else if (i == 14) cp_wait<1>(); else cp_wait<0>();
        __syncthreads();
        if (i + 3 < 16) load_stage((i + 3) & 3, (i + 3) * 64);   // slot freed at i-1

        const uint32_t sQh = sb + (i & 3) * QK_STAGE;
        const uint32_t sQl = sQh + 16384;
        const uint32_t sKh = sQh + 32768;

        #pragma unroll
        for (int ks = 0; ks < 4; ks++) {
            uint32_t ah[2][4], al[2][4], bh[2][4];
            #pragma unroll
            for (int mt = 0; mt < 2; mt++) {
                uint32_t off = SW128((uint32_t)((arow_base + mt * 16) * 128 + (ks * 2 + a_k8) * 16));
                ldsm4(ah[mt], sQh + off);
                ldsm4(al[mt], sQl + off);
            }
            #pragma unroll
            for (int np = 0; np < 2; np++) {
                uint32_t off = SW128((uint32_t)((brow_base + np * 16) * 128 + (ks * 2 + b_k8) * 16));
                ldsm4(bh[np], sKh + off);
            }
            #pragma unroll
            for (int mt = 0; mt < 2; mt++)
                #pragma unroll
                for (int nt = 0; nt < 4; nt++) {
                    const int np = nt >> 1, h = (nt & 1) * 2;
                    mma_f16(acc[mt][nt], ah[mt], bh[np][h], bh[np][h + 1]);
                    mma_f16(acc[mt][nt], al[mt], bh[np][h], bh[np][h + 1]);
                }
        }
    }

    __syncthreads();   // all MMA reads done; stage area reusable

    const int quad = lane >> 2, qid = lane & 3;
    float* stage = (float*)smem;                 // pitch 132 floats
    float* red = (float*)(smem + QK_RED);        // [128][4]

    float rs0[2] = {}, rs1[2] = {};
    #pragma unroll
    for (int mt = 0; mt < 2; mt++) {
        const int r0 = warp_m * 32 + mt * 16 + quad;
        #pragma unroll
        for (int nt = 0; nt < 4; nt++) {
            const int c = warp_n * 32 + nt * 8 + qid * 2;
            float d0 = __expf(acc[mt][nt][0] * SCALE);
            float d1 = __expf(acc[mt][nt][1] * SCALE);
            float d2 = __expf(acc[mt][nt][2] * SCALE);
            float d3 = __expf(acc[mt][nt][3] * SCALE);
            rs0[mt] += d0 + d1; rs1[mt] += d2 + d3;
            *(float2*)&stage[r0 * 132 + c]       = make_float2(d0, d1);
            *(float2*)&stage[(r0 + 8) * 132 + c] = make_float2(d2, d3);
        }
    }
    #pragma unroll
    for (int mt = 0; mt < 2; mt++) {
        float s0 = rs0[mt], s1 = rs1[mt];
        s0 += __shfl_xor_sync(0xFFFFFFFFu, s0, 1);
        s0 += __shfl_xor_sync(0xFFFFFFFFu, s0, 2);
        s1 += __shfl_xor_sync(0xFFFFFFFFu, s1, 1);
        s1 += __shfl_xor_sync(0xFFFFFFFFu, s1, 2);
        if (qid == 0) {
            const int r0 = warp_m * 32 + mt * 16 + quad;
            red[r0 * 4 + warp_n] = s0;
            red[(r0 + 8) * 4 + warp_n] = s1;
        }
    }
    __syncthreads();

    if (t < 128) {
        float s = red[t * 4 + 0] + red[t * 4 + 1] + red[t * 4 + 2] + red[t * 4 + 3];
        g_rowpart[((size_t)b * TSEQ + tm * 128 + t) * NT + tn] = s;
    }

    float* op = out + ((size_t)b * TSEQ + tm * 128) * 1024 + tn * 128;
    const int j = t & 31;
    #pragma unroll
    for (int r = t >> 5; r < 128; r += 16) {
        float4 v = *(float4*)&stage[r * 132 + j * 4];
        *(float4*)(op + (size_t)r * 1024 + j * 4) = v;
    }
}

// ---------------------------------------------------------------------------
// P*V: O[128,128] = P[128,1024] Vt[128,1024]^T, fp16 single-pass.
// 2-stage k64 (64KB smem), 2 CTAs/SM, direct register->gmem epilogue.
// ---------------------------------------------------------------------------
#define PV_SMEM 65536

__global__ void __launch_bounds__(256, 2) pv_gemm(float* __restrict__ out) {
    extern __shared__ __align__(1024) char smem[];
    const uint32_t sb = smem_u32(smem);
    const int t = threadIdx.x, wid = t >> 5, lane = t & 31;
    const int tn = blockIdx.x, tm = blockIdx.y, b = blockIdx.z;

    const __half* srcs[2] = {
        g_Pf16  + ((size_t)b * TSEQ + tm * 128) * 1024,
        g_Vtf16 + ((size_t)b * DDIM + tn * 128) * 1024
    };

    const int lr = t >> 3;
    const int lc = t & 7;
    const uint32_t dsw = SW128((uint32_t)(lr * 128 + lc * 16));

    auto load_stage = [&](int slot, int k0) {
        const uint32_t s0 = sb + slot * 32768;
        #pragma unroll
        for (int buf = 0; buf < 2; buf++) {
            const __half* p = srcs[buf] + k0 + lc * 8;
            #pragma unroll
            for (int j = 0; j < 4; j++)
                cp16(s0 + buf * 16384 + dsw + j * 4096, p + (size_t)(lr + 32 * j) * 1024);
        }
        cp_commit();
    };

    const int warp_m = wid >> 2, warp_n = wid & 3;
    const int mrow = lane & 7, mid = lane >> 3;
    const int arow_base = warp_m * 64 + mrow + (mid & 1) * 8;
    const int a_k8 = mid >> 1;
    const int brow_base = warp_n * 32 + mrow + (mid >> 1) * 8;
    const int b_k8 = mid & 1;

    float acc[4][4][4] = {};

    load_stage(0, 0);
    load_stage(1, 64);

    for (int i = 0; i < 16; i++) {
        if (i == 15) cp_wait<0>(); else cp_wait<1>();
        __syncthreads();

        const uint32_t sA = sb + (i & 1) * 32768;
        const uint32_t sB = sA + 16384;

        #pragma unroll
        for (int ks = 0; ks < 4; ks++) {
            uint32_t ah[4][4], bh[2][4];
            #pragma unroll
            for (int mt = 0; mt < 4; mt++) {
                uint32_t off = SW128((uint32_t)((arow_base + mt * 16) * 128 + (ks * 2 + a_k8) * 16));
                ldsm4(ah[mt], sA + off);
            }
            #pragma unroll
            for (int np = 0; np < 2; np++) {
                uint32_t off = SW128((uint32_t)((brow_base + np * 16) * 128 + (ks * 2 + b_k8) * 16));
                ldsm4(bh[np], sB + off);
            }
            #pragma unroll
            for (int mt = 0; mt < 4; mt++)
                #pragma unroll
                for (int nt = 0; nt < 4; nt++) {
                    const int np = nt >> 1, h = (nt & 1) * 2;
                    mma_f16(acc[mt][nt], ah[mt], bh[np][h], bh[np][h + 1]);
                }
        }

        __syncthreads();
        if (i + 2 < 16) load_stage(i & 1, (i + 2) * 64);
    }

    // direct register -> gmem epilogue
    const int quad = lane >> 2, qid = lane & 3;
    float* op = out + ((size_t)b * TSEQ + tm * 128) * 1024 + tn * 128;
    #pragma unroll
    for (int mt = 0; mt < 4; mt++) {
        const int r0 = warp_m * 64 + mt * 16 + quad;
        #pragma unroll
        for (int nt = 0; nt < 4; nt++) {
            const int c = warp_n * 32 + nt * 8 + qid * 2;
            *(float2*)(op + (size_t)r0 * 1024 + c)       = make_float2(acc[mt][nt][0], acc[mt][nt][1]);
            *(float2*)(op + (size_t)(r0 + 8) * 1024 + c) = make_float2(acc[mt][nt][2], acc[mt][nt][3]);
        }
    }
}

// ---------------------------------------------------------------------------
// norm: scores /= rowsum (fp32 in place), emit fp16 P
// ---------------------------------------------------------------------------
__global__ __launch_bounds__(256) void norm_kernel(float* __restrict__ scores) {
    const int row = blockIdx.x;
    __shared__ float sinv;
    if (threadIdx.x < 8) {
        float s = g_rowpart[(size_t)row * NT + threadIdx.x];
        #pragma unroll
        for (int o = 4; o > 0; o >>= 1) s += __shfl_xor_sync(0xFFu, s, o);
        if (threadIdx.x == 0) sinv = 1.0f / s;
    }
    __syncthreads();
    const float inv = sinv;
    const size_t base = (size_t)row * TSEQ + threadIdx.x * 4;
    float4 v = *(float4*)(scores + base);
    v.x *= inv; v.y *= inv; v.z *= inv; v.w *= inv;
    *(float4*)(scores + base) = v;
    __half2 p0 = __floats2half2_rn(v.x, v.y);
    __half2 p1 = __floats2half2_rn(v.z, v.w);
    *(uint2*)(g_Pf16 + base) = make_uint2(*(uint32_t*)&p0, *(uint32_t*)&p1);
}

// ---------------------------------------------------------------------------
extern "C" void kernel_launch(void* const* d_in, const int* in_sizes, int n_in,
                              void* d_out, int out_size)
{
    const float* Q = (const float*)d_in[0];
    const float* K = (const float*)d_in[1];
    const float* V = (const float*)d_in[2];
    float* summaries = (float*)d_out;
    float* scores    = (float*)d_out + NELEM;

    cudaFuncSetAttribute(qk_gemm, cudaFuncAttributeMaxDynamicSharedMemorySize, QK_SMEM);
    cudaFuncSetAttribute(pv_gemm, cudaFuncAttributeMaxDynamicSharedMemorySize, PV_SMEM);

    const int cblocks = (int)(NELEM / (256 * 4));
    conv_q<<<cblocks, 256>>>(Q);
    conv_k<<<cblocks, 256>>>(K);
    vtrans<<<dim3(32, 32, 16), 256>>>(V);

    dim3 ggrid(8, 8, 16);
    qk_gemm<<<ggrid, 512, QK_SMEM>>>(scores);
    norm_kernel<<<BATCH * TSEQ, 256>>>(scores);
    pv_gemm<<<ggrid, 256, PV_SMEM>>>(summaries);
}

// round 10
// speedup vs baseline: 1.2399x; 1.2399x over previous
#include <cuda_runtime.h>
#include <cuda_bf16.h>
#include <cuda_fp16.h>
#include <cstdint>
#include <cstddef>

// DotAttention B=16, T=1024, D=1024 fp32 (plain sm_100, mma.sync path).
// QK^T: fp16 single-pass (Qh*Kh), 256 threads, 4-stage k64 pipeline.
// P*V : fp16 single-pass, 2 CTAs/SM.
// Error model: scores ~4.6e-4, summaries ~5.5e-4 (threshold 1e-3).

#define BATCH 16
#define TSEQ  1024
#define DDIM  1024
#define NT    8
static constexpr float SCALE = 0.03125f;

#define NELEM ((size_t)BATCH * TSEQ * DDIM)   // 16M

__device__ __align__(16) __half g_Qf16[NELEM];
__device__ __align__(16) __half g_Kf16[NELEM];
__device__ __align__(16) __half g_Vtf16[NELEM];  // V^T per batch: [b][d][s]
__device__ __align__(16) __half g_Pf16[NELEM];   // normalized P fp16
__device__ float g_rowpart[BATCH * TSEQ * NT];

// ---------------------------------------------------------------------------
__device__ __forceinline__ uint32_t smem_u32(const void* p) {
    uint32_t a;
    asm("{ .reg .u64 t; cvta.to.shared.u64 t, %1; cvt.u32.u64 %0, t; }" : "=r"(a) : "l"(p));
    return a;
}
__device__ __forceinline__ void cp16(uint32_t dst, const void* src) {
    asm volatile("cp.async.cg.shared.global [%0], [%1], 16;" :: "r"(dst), "l"(src));
}
__device__ __forceinline__ void cp_commit() { asm volatile("cp.async.commit_group;" ::: "memory"); }
template <int N> __device__ __forceinline__ void cp_wait() {
    asm volatile("cp.async.wait_group %0;" :: "n"(N) : "memory");
}
__device__ __forceinline__ void ldsm4(uint32_t (&r)[4], uint32_t addr) {
    asm volatile("ldmatrix.sync.aligned.m8n8.x4.shared.b16 {%0,%1,%2,%3}, [%4];"
        : "=r"(r[0]), "=r"(r[1]), "=r"(r[2]), "=r"(r[3]) : "r"(addr));
}
__device__ __forceinline__ void mma_f16(float (&d)[4], const uint32_t (&a)[4],
                                        uint32_t b0, uint32_t b1) {
    asm volatile(
        "mma.sync.aligned.m16n8k16.row.col.f32.f16.f16.f32 "
        "{%0,%1,%2,%3}, {%4,%5,%6,%7}, {%8,%9}, {%0,%1,%2,%3};"
        : "+f"(d[0]), "+f"(d[1]), "+f"(d[2]), "+f"(d[3])
        : "r"(a[0]), "r"(a[1]), "r"(a[2]), "r"(a[3]), "r"(b0), "r"(b1));
}
#define SW128(o) ((o) ^ (((o) >> 3) & 0x70))

// ---------------------------------------------------------------------------
// conv: fp32 -> fp16 single (Q and K)
// ---------------------------------------------------------------------------
template <int WHICH>   // 0: Q, 1: K
__global__ __launch_bounds__(256) void conv_f16(const float* __restrict__ x) {
    __half* dst = (WHICH == 0) ? g_Qf16 : g_Kf16;
    size_t i = ((size_t)blockIdx.x * 256 + threadIdx.x) * 4;
    float4 v = *(const float4*)(x + i);
    __half2 p0 = __floats2half2_rn(v.x, v.y);
    __half2 p1 = __floats2half2_rn(v.z, v.w);
    *(uint2*)(dst + i) = make_uint2(*(uint32_t*)&p0, *(uint32_t*)&p1);
}

// ---------------------------------------------------------------------------
// vtrans: V [b][s][d] -> V^T fp16 [b][d][s]
// ---------------------------------------------------------------------------
__global__ __launch_bounds__(256) void vtrans(const float* __restrict__ V) {
    __shared__ float tile[32][33];
    int b = blockIdx.z, s0 = blockIdx.y * 32, d0 = blockIdx.x * 32;
    int t = threadIdx.x;
    int r = t >> 3, c4 = t & 7;
    const float* Vb = V + ((size_t)b * TSEQ + s0) * DDIM + d0;
    float4 v = *(const float4*)(Vb + (size_t)r * DDIM + c4 * 4);
    tile[r][c4 * 4 + 0] = v.x; tile[r][c4 * 4 + 1] = v.y;
    tile[r][c4 * 4 + 2] = v.z; tile[r][c4 * 4 + 3] = v.w;
    __syncthreads();
    int dr = t >> 3, s4 = t & 7;
    float x0 = tile[s4 * 4 + 0][dr], x1 = tile[s4 * 4 + 1][dr];
    float x2 = tile[s4 * 4 + 2][dr], x3 = tile[s4 * 4 + 3][dr];
    __half2 p0 = __floats2half2_rn(x0, x1);
    __half2 p1 = __floats2half2_rn(x2, x3);
    size_t off = ((size_t)b * DDIM + d0 + dr) * TSEQ + s0 + s4 * 4;
    *(uint2*)(g_Vtf16 + off) = make_uint2(*(uint32_t*)&p0, *(uint32_t*)&p1);
}

// ---------------------------------------------------------------------------
// QK^T: C[128,128] = Q[128,1024] K[128,1024]^T, fp16 single-term.
// 256 threads / 8 warps = 2m x 4n, warp tile 64x32. 4-stage k64 pipeline
// (32KB/stage). Epilogue: exp, rowsums, staged coalesced store.
// ---------------------------------------------------------------------------
#define QK_STAGE 32768
#define QK_SMEM  (4 * QK_STAGE + 2048)
#define QK_RED   (4 * QK_STAGE)

__global__ void __launch_bounds__(256, 1) qk_gemm(float* __restrict__ out) {
    extern __shared__ __align__(1024) char smem[];
    const uint32_t sb = smem_u32(smem);
    const int t = threadIdx.x, wid = t >> 5, lane = t & 31;
    const int tn = blockIdx.x, tm = blockIdx.y, b = blockIdx.z;

    const size_t aoff = ((size_t)b * TSEQ + tm * 128) * 1024;
    const size_t boff = ((size_t)b * TSEQ + tn * 128) * 1024;
    const __half* srcs[2] = {g_Qf16 + aoff, g_Kf16 + boff};

    const int lr = t >> 3;          // 0..31 base row
    const int lc = t & 7;
    const uint32_t dsw = SW128((uint32_t)(lr * 128 + lc * 16));

    auto load_stage = [&](int slot, int k0) {
        const uint32_t s0 = sb + slot * QK_STAGE;
        #pragma unroll
        for (int buf = 0; buf < 2; buf++) {
            const __half* p = srcs[buf] + k0 + lc * 8;
            #pragma unroll
            for (int j = 0; j < 4; j++)
                cp16(s0 + buf * 16384 + dsw + j * 4096, p + (size_t)(lr + 32 * j) * 1024);
        }
        cp_commit();
    };

    const int warp_m = wid >> 2, warp_n = wid & 3;
    const int mrow = lane & 7, mid = lane >> 3;
    const int arow_base = warp_m * 64 + mrow + (mid & 1) * 8;
    const int a_k8 = mid >> 1;
    const int brow_base = warp_n * 32 + mrow + (mid >> 1) * 8;
    const int b_k8 = mid & 1;

    float acc[4][4][4] = {};

    load_stage(0, 0);
    load_stage(1, 64);
    load_stage(2, 128);

    for (int i = 0; i < 16; i++) {
        if (i < 14) cp_wait<2>(); else if (i == 14) cp_wait<1>(); else cp_wait<0>();
        __syncthreads();
        if (i + 3 < 16) load_stage((i + 3) & 3, (i + 3) * 64);   // slot freed at i-1

        const uint32_t sQ = sb + (i & 3) * QK_STAGE;
        const uint32_t sK = sQ + 16384;

        #pragma unroll
        for (int ks = 0; ks < 4; ks++) {
            uint32_t ah[4][4], bh[2][4];
            #pragma unroll
            for (int mt = 0; mt < 4; mt++) {
                uint32_t off = SW128((uint32_t)((arow_base + mt * 16) * 128 + (ks * 2 + a_k8) * 16));
                ldsm4(ah[mt], sQ + off);
            }
            #pragma unroll
            for (int np = 0; np < 2; np++) {
                uint32_t off = SW128((uint32_t)((brow_base + np * 16) * 128 + (ks * 2 + b_k8) * 16));
                ldsm4(bh[np], sK + off);
            }
            #pragma unroll
            for (int mt = 0; mt < 4; mt++)
                #pragma unroll
                for (int nt = 0; nt < 4; nt++) {
                    const int np = nt >> 1, h = (nt & 1) * 2;
                    mma_f16(acc[mt][nt], ah[mt], bh[np][h], bh[np][h + 1]);
                }
        }
    }

    __syncthreads();   // all MMA reads done; stage area reusable

    const int quad = lane >> 2, qid = lane & 3;
    float* stage = (float*)smem;                 // pitch 132 floats
    float* red = (float*)(smem + QK_RED);        // [128][4]

    float rs0[4] = {}, rs1[4] = {};
    #pragma unroll
    for (int mt = 0; mt < 4; mt++) {
        const int r0 = warp_m * 64 + mt * 16 + quad;
        #pragma unroll
        for (int nt = 0; nt < 4; nt++) {
            const int c = warp_n * 32 + nt * 8 + qid * 2;
            float d0 = __expf(acc[mt][nt][0] * SCALE);
            float d1 = __expf(acc[mt][nt][1] * SCALE);
            float d2 = __expf(acc[mt][nt][2] * SCALE);
            float d3 = __expf(acc[mt][nt][3] * SCALE);
            rs0[mt] += d0 + d1; rs1[mt] += d2 + d3;
            *(float2*)&stage[r0 * 132 + c]       = make_float2(d0, d1);
            *(float2*)&stage[(r0 + 8) * 132 + c] = make_float2(d2, d3);
        }
    }
    #pragma unroll
    for (int mt = 0; mt < 4; mt++) {
        float s0 = rs0[mt], s1 = rs1[mt];
        s0 += __shfl_xor_sync(0xFFFFFFFFu, s0, 1);
        s0 += __shfl_xor_sync(0xFFFFFFFFu, s0, 2);
        s1 += __shfl_xor_sync(0xFFFFFFFFu, s1, 1);
        s1 += __shfl_xor_sync(0xFFFFFFFFu, s1, 2);
        if (qid == 0) {
            const int r0 = warp_m * 64 + mt * 16 + quad;
            red[r0 * 4 + warp_n] = s0;
            red[(r0 + 8) * 4 + warp_n] = s1;
        }
    }
    __syncthreads();

    if (t < 128) {
        float s = red[t * 4 + 0] + red[t * 4 + 1] + red[t * 4 + 2] + red[t * 4 + 3];
        g_rowpart[((size_t)b * TSEQ + tm * 128 + t) * NT + tn] = s;
    }

    float* op = out + ((size_t)b * TSEQ + tm * 128) * 1024 + tn * 128;
    const int j = t & 31;
    #pragma unroll
    for (int r = t >> 5; r < 128; r += 8) {
        float4 v = *(float4*)&stage[r * 132 + j * 4];
        *(float4*)(op + (size_t)r * 1024 + j * 4) = v;
    }
}

// ---------------------------------------------------------------------------
// P*V: O[128,128] = P[128,1024] Vt[128,1024]^T, fp16 single-pass.
// 2-stage k64 (64KB smem), 2 CTAs/SM, direct register->gmem epilogue.
// ---------------------------------------------------------------------------
#define PV_SMEM 65536

__global__ void __launch_bounds__(256, 2) pv_gemm(float* __restrict__ out) {
    extern __shared__ __align__(1024) char smem[];
    const uint32_t sb = smem_u32(smem);
    const int t = threadIdx.x, wid = t >> 5, lane = t & 31;
    const int tn = blockIdx.x, tm = blockIdx.y, b = blockIdx.z;

    const __half* srcs[2] = {
        g_Pf16  + ((size_t)b * TSEQ + tm * 128) * 1024,
        g_Vtf16 + ((size_t)b * DDIM + tn * 128) * 1024
    };

    const int lr = t >> 3;
    const int lc = t & 7;
    const uint32_t dsw = SW128((uint32_t)(lr * 128 + lc * 16));

    auto load_stage = [&](int slot, int k0) {
        const uint32_t s0 = sb + slot * 32768;
        #pragma unroll
        for (int buf = 0; buf < 2; buf++) {
            const __half* p = srcs[buf] + k0 + lc * 8;
            #pragma unroll
            for (int j = 0; j < 4; j++)
                cp16(s0 + buf * 16384 + dsw + j * 4096, p + (size_t)(lr + 32 * j) * 1024);
        }
        cp_commit();
    };

    const int warp_m = wid >> 2, warp_n = wid & 3;
    const int mrow = lane & 7, mid = lane >> 3;
    const int arow_base = warp_m * 64 + mrow + (mid & 1) * 8;
    const int a_k8 = mid >> 1;
    const int brow_base = warp_n * 32 + mrow + (mid >> 1) * 8;
    const int b_k8 = mid & 1;

    float acc[4][4][4] = {};

    load_stage(0, 0);
    load_stage(1, 64);

    for (int i = 0; i < 16; i++) {
        if (i == 15) cp_wait<0>(); else cp_wait<1>();
        __syncthreads();

        const uint32_t sA = sb + (i & 1) * 32768;
        const uint32_t sB = sA + 16384;

        #pragma unroll
        for (int ks = 0; ks < 4; ks++) {
            uint32_t ah[4][4], bh[2][4];
            #pragma unroll
            for (int mt = 0; mt < 4; mt++) {
                uint32_t off = SW128((uint32_t)((arow_base + mt * 16) * 128 + (ks * 2 + a_k8) * 16));
                ldsm4(ah[mt], sA + off);
            }
            #pragma unroll
            for (int np = 0; np < 2; np++) {
                uint32_t off = SW128((uint32_t)((brow_base + np * 16) * 128 + (ks * 2 + b_k8) * 16));
                ldsm4(bh[np], sB + off);
            }
            #pragma unroll
            for (int mt = 0; mt < 4; mt++)
                #pragma unroll
                for (int nt = 0; nt < 4; nt++) {
                    const int np = nt >> 1, h = (nt & 1) * 2;
                    mma_f16(acc[mt][nt], ah[mt], bh[np][h], bh[np][h + 1]);
                }
        }

        __syncthreads();
        if (i + 2 < 16) load_stage(i & 1, (i + 2) * 64);
    }

    // direct register -> gmem epilogue
    const int quad = lane >> 2, qid = lane & 3;
    float* op = out + ((size_t)b * TSEQ + tm * 128) * 1024 + tn * 128;
    #pragma unroll
    for (int mt = 0; mt < 4; mt++) {
        const int r0 = warp_m * 64 + mt * 16 + quad;
        #pragma unroll
        for (int nt = 0; nt < 4; nt++) {
            const int c = warp_n * 32 + nt * 8 + qid * 2;
            *(float2*)(op + (size_t)r0 * 1024 + c)       = make_float2(acc[mt][nt][0], acc[mt][nt][1]);
            *(float2*)(op + (size_t)(r0 + 8) * 1024 + c) = make_float2(acc[mt][nt][2], acc[mt][nt][3]);
        }
    }
}

// ---------------------------------------------------------------------------
// norm: scores /= rowsum (fp32 in place), emit fp16 P
// ---------------------------------------------------------------------------
__global__ __launch_bounds__(256) void norm_kernel(float* __restrict__ scores) {
    const int row = blockIdx.x;
    __shared__ float sinv;
    if (threadIdx.x < 8) {
        float s = g_rowpart[(size_t)row * NT + threadIdx.x];
        #pragma unroll
        for (int o = 4; o > 0; o >>= 1) s += __shfl_xor_sync(0xFFu, s, o);
        if (threadIdx.x == 0) sinv = 1.0f / s;
    }
    __syncthreads();
    const float inv = sinv;
    const size_t base = (size_t)row * TSEQ + threadIdx.x * 4;
    float4 v = *(float4*)(scores + base);
    v.x *= inv; v.y *= inv; v.z *= inv; v.w *= inv;
    *(float4*)(scores + base) = v;
    __half2 p0 = __floats2half2_rn(v.x, v.y);
    __half2 p1 = __floats2half2_rn(v.z, v.w);
    *(uint2*)(g_Pf16 + base) = make_uint2(*(uint32_t*)&p0, *(uint32_t*)&p1);
}

// ---------------------------------------------------------------------------
extern "C" void kernel_launch(void* const* d_in, const int* in_sizes, int n_in,
                              void* d_out, int out_size)
{
    const float* Q = (const float*)d_in[0];
    const float* K = (const float*)d_in[1];
    const float* V = (const float*)d_in[2];
    float* summaries = (float*)d_out;
    float* scores    = (float*)d_out + NELEM;

    cudaFuncSetAttribute(qk_gemm, cudaFuncAttributeMaxDynamicSharedMemorySize, QK_SMEM);
    cudaFuncSetAttribute(pv_gemm, cudaFuncAttributeMaxDynamicSharedMemorySize, PV_SMEM);

    const int cblocks = (int)(NELEM / (256 * 4));
    conv_f16<0><<<cblocks, 256>>>(Q);
    conv_f16<1><<<cblocks, 256>>>(K);
    vtrans<<<dim3(32, 32, 16), 256>>>(V);

    dim3 ggrid(8, 8, 16);
    qk_gemm<<<ggrid, 256, QK_SMEM>>>(scores);
    norm_kernel<<<BATCH * TSEQ, 256>>>(scores);
    pv_gemm<<<ggrid, 256, PV_SMEM>>>(summaries);
}